// round 3
// baseline (speedup 1.0000x reference)
#include <cuda_runtime.h>
#include <cuda_bf16.h>
#include <math.h>

// ---------------------------------------------------------------------------
// GCN: h1 = relu(gcnconv(x, W1,b1)); h2 = sigmoid(gcnconv(h1, W2,b2));
//      h3 = relu(h2@W3+b3); h4 = relu(h3@W4+b4); out = h4@W5+b5
// gcnconv factorization: out[d] = dinv[d] * ( sum_{e: dst=d} g[src] + g[d] ),
//   g[i] = dinv[i] * (x[i]@W),  dinv[i] = rsqrt(indeg(i)+1)
// ---------------------------------------------------------------------------

#define MAX_N 1000000
#define NTHREADS 256

// scratch (static device allocations are allowed)
__device__ int    g_deg[MAX_N];
__device__ float  g_dinv[MAX_N];
__device__ float4 g_feat[MAX_N];   // dinv-prescaled features (gather source)
__device__ float4 g_acc[MAX_N];    // aggregation accumulator

// packed weights in constant memory
// W1:0(8) b1:8(4) W2:12(12) b2:24(3) W3:27(12) b3:39(4) W4:43(12) b4:55(3) W5:58(3) b5:61(1)
__constant__ float cW[64];

__device__ __forceinline__ void red4(float4* p, float4 v) {
    asm volatile("red.global.add.v4.f32 [%0], {%1,%2,%3,%4};"
                 :: "l"(p), "f"(v.x), "f"(v.y), "f"(v.z), "f"(v.w) : "memory");
}

// ---- degree count: deg[dst] += 1 over all edges (deg was memset to 0) ----
__global__ void k_deg(const int* __restrict__ dst, int E) {
    int i = (blockIdx.x * blockDim.x + threadIdx.x) * 4;
    if (i + 3 < E) {
        int4 d = *(const int4*)(dst + i);
        atomicAdd(&g_deg[d.x], 1);
        atomicAdd(&g_deg[d.y], 1);
        atomicAdd(&g_deg[d.z], 1);
        atomicAdd(&g_deg[d.w], 1);
    } else {
        for (int j = i; j < E; j++) atomicAdd(&g_deg[dst[j]], 1);
    }
}

// ---- node pass 1: dinv, g = dinv*(x@W1), acc = g (self loop) ----
__global__ void k_node1(const float* __restrict__ x, int N) {
    int i = blockIdx.x * blockDim.x + threadIdx.x;
    if (i >= N) return;
    float dinv = rsqrtf((float)(g_deg[i] + 1));
    float2 xv = ((const float2*)x)[i];
    float4 h;
    h.x = dinv * (xv.x * cW[0] + xv.y * cW[4]);
    h.y = dinv * (xv.x * cW[1] + xv.y * cW[5]);
    h.z = dinv * (xv.x * cW[2] + xv.y * cW[6]);
    h.w = dinv * (xv.x * cW[3] + xv.y * cW[7]);
    g_dinv[i] = dinv;
    g_feat[i] = h;
    g_acc[i]  = h;
}

// ---- edge scatter: acc[dst] += g[src] (vector reduction) ----
__global__ void k_scatter(const int* __restrict__ src, const int* __restrict__ dst, int E) {
    int i = (blockIdx.x * blockDim.x + threadIdx.x) * 4;
    if (i + 3 < E) {
        int4 s = *(const int4*)(src + i);
        int4 d = *(const int4*)(dst + i);
        float4 a0 = g_feat[s.x];
        float4 a1 = g_feat[s.y];
        float4 a2 = g_feat[s.z];
        float4 a3 = g_feat[s.w];
        red4(&g_acc[d.x], a0);
        red4(&g_acc[d.y], a1);
        red4(&g_acc[d.z], a2);
        red4(&g_acc[d.w], a3);
    } else {
        for (int j = i; j < E; j++) red4(&g_acc[dst[j]], g_feat[src[j]]);
    }
}

// ---- node pass 2: h1 = relu(dinv*acc + b1); g2 = dinv*(h1@W2); acc = g2 ----
__global__ void k_node2(int N) {
    int i = blockIdx.x * blockDim.x + threadIdx.x;
    if (i >= N) return;
    float dinv = g_dinv[i];
    float4 a = g_acc[i];
    float h0 = fmaxf(a.x * dinv + cW[8],  0.0f);
    float h1 = fmaxf(a.y * dinv + cW[9],  0.0f);
    float h2 = fmaxf(a.z * dinv + cW[10], 0.0f);
    float h3 = fmaxf(a.w * dinv + cW[11], 0.0f);
    // W2 [4,3] row-major at cW[12..23]
    float4 g;
    g.x = dinv * (h0 * cW[12] + h1 * cW[15] + h2 * cW[18] + h3 * cW[21]);
    g.y = dinv * (h0 * cW[13] + h1 * cW[16] + h2 * cW[19] + h3 * cW[22]);
    g.z = dinv * (h0 * cW[14] + h1 * cW[17] + h2 * cW[20] + h3 * cW[23]);
    g.w = 0.0f;
    g_feat[i] = g;
    g_acc[i]  = g;
}

// ---- node pass 3: sigmoid + MLP head, write output ----
__global__ void k_node3(float* __restrict__ out, int N) {
    int i = blockIdx.x * blockDim.x + threadIdx.x;
    if (i >= N) return;
    float dinv = g_dinv[i];
    float4 a = g_acc[i];
    // sigmoid(dinv*acc + b2)
    float s0 = 1.0f / (1.0f + expf(-(a.x * dinv + cW[24])));
    float s1 = 1.0f / (1.0f + expf(-(a.y * dinv + cW[25])));
    float s2 = 1.0f / (1.0f + expf(-(a.z * dinv + cW[26])));
    // h3 = relu(s @ W3[3,4] + b3), W3 at 27, b3 at 39
    float u0 = fmaxf(s0 * cW[27] + s1 * cW[31] + s2 * cW[35] + cW[39], 0.0f);
    float u1 = fmaxf(s0 * cW[28] + s1 * cW[32] + s2 * cW[36] + cW[40], 0.0f);
    float u2 = fmaxf(s0 * cW[29] + s1 * cW[33] + s2 * cW[37] + cW[41], 0.0f);
    float u3 = fmaxf(s0 * cW[30] + s1 * cW[34] + s2 * cW[38] + cW[42], 0.0f);
    // h4 = relu(u @ W4[4,3] + b4), W4 at 43, b4 at 55
    float v0 = fmaxf(u0 * cW[43] + u1 * cW[46] + u2 * cW[49] + u3 * cW[52] + cW[55], 0.0f);
    float v1 = fmaxf(u0 * cW[44] + u1 * cW[47] + u2 * cW[50] + u3 * cW[53] + cW[56], 0.0f);
    float v2 = fmaxf(u0 * cW[45] + u1 * cW[48] + u2 * cW[51] + u3 * cW[54] + cW[57], 0.0f);
    // out = v @ W5[3,1] + b5, W5 at 58, b5 at 61
    out[i] = v0 * cW[58] + v1 * cW[59] + v2 * cW[60] + cW[61];
}

extern "C" void kernel_launch(void* const* d_in, const int* in_sizes, int n_in,
                              void* d_out, int out_size) {
    const float* x    = (const float*)d_in[0];
    const int*   eidx = (const int*)d_in[1];
    int N = in_sizes[0] / 2;
    int E = in_sizes[1] / 2;
    const int* src = eidx;
    const int* dst = eidx + E;
    float* out = (float*)d_out;

    // weights -> constant memory (D2D memcpy nodes, graph-capturable)
    cudaMemcpyToSymbolAsync(cW, d_in[2],  8 * sizeof(float),  0 * sizeof(float), cudaMemcpyDeviceToDevice, 0); // W1
    cudaMemcpyToSymbolAsync(cW, d_in[3],  4 * sizeof(float),  8 * sizeof(float), cudaMemcpyDeviceToDevice, 0); // b1
    cudaMemcpyToSymbolAsync(cW, d_in[4], 12 * sizeof(float), 12 * sizeof(float), cudaMemcpyDeviceToDevice, 0); // W2
    cudaMemcpyToSymbolAsync(cW, d_in[5],  3 * sizeof(float), 24 * sizeof(float), cudaMemcpyDeviceToDevice, 0); // b2
    cudaMemcpyToSymbolAsync(cW, d_in[6], 12 * sizeof(float), 27 * sizeof(float), cudaMemcpyDeviceToDevice, 0); // W3
    cudaMemcpyToSymbolAsync(cW, d_in[7],  4 * sizeof(float), 39 * sizeof(float), cudaMemcpyDeviceToDevice, 0); // b3
    cudaMemcpyToSymbolAsync(cW, d_in[8], 12 * sizeof(float), 43 * sizeof(float), cudaMemcpyDeviceToDevice, 0); // W4
    cudaMemcpyToSymbolAsync(cW, d_in[9],  3 * sizeof(float), 55 * sizeof(float), cudaMemcpyDeviceToDevice, 0); // b4
    cudaMemcpyToSymbolAsync(cW, d_in[10], 3 * sizeof(float), 58 * sizeof(float), cudaMemcpyDeviceToDevice, 0); // W5
    cudaMemcpyToSymbolAsync(cW, d_in[11], 1 * sizeof(float), 61 * sizeof(float), cudaMemcpyDeviceToDevice, 0); // b5

    // zero degree counters
    void* degPtr = nullptr;
    cudaGetSymbolAddress(&degPtr, g_deg);
    cudaMemsetAsync(degPtr, 0, N * sizeof(int), 0);

    int nodeBlocks = (N + NTHREADS - 1) / NTHREADS;
    int edgeBlocks = ((E + 3) / 4 + NTHREADS - 1) / NTHREADS;

    k_deg    <<<edgeBlocks, NTHREADS>>>(dst, E);
    k_node1  <<<nodeBlocks, NTHREADS>>>(x, N);
    k_scatter<<<edgeBlocks, NTHREADS>>>(src, dst, E);
    k_node2  <<<nodeBlocks, NTHREADS>>>(N);
    k_scatter<<<edgeBlocks, NTHREADS>>>(src, dst, E);
    k_node3  <<<nodeBlocks, NTHREADS>>>(out, N);
}